// round 1
// baseline (speedup 1.0000x reference)
#include <cuda_runtime.h>
#include <cstdint>

#define TB      256
#define TILE_H  8
#define TILE_W  32
#define CIN     64
#define COUT    64
#define HH      512
#define WW      512
#define HALO_H  (TILE_H + 2)
#define HALO_W  (TILE_W + 2)
#define XS_ELEMS (CIN * HALO_H * HALO_W)       // 64*10*34 = 21760 floats
#define SMEM_BYTES ((XS_ELEMS + CIN * COUT) * 4) // 87040 + 16384 = 103424 B

// a(i) = 1/sqrt(#valid window positions along one axis): rsqrt(2) at border, rsqrt(3) interior
__device__ __forceinline__ float axis_a(int i) {
    return (i == 0 || i == HH - 1) ? 0.70710678118654752f : 0.57735026918962576f;
}

__global__ void __launch_bounds__(TB) gcn_fused_kernel(
    const float* __restrict__ x,     // [B, 64, 512, 512]
    const float* __restrict__ wmat,  // [64, 64]  (c, o)
    float* __restrict__ out)         // [B, 64, 512, 512]
{
    extern __shared__ float smem[];
    float* xs = smem;                 // [CIN][HALO_H][HALO_W], pre-scaled by dinv(q), 0 outside
    float* Ws = smem + XS_ELEMS;      // [CIN][COUT]

    const int bx  = blockIdx.x;       // w tile
    const int by  = blockIdx.y;       // h tile
    const int b   = blockIdx.z;
    const int tid = threadIdx.x;

    // --- load W into smem ---
    #pragma unroll
    for (int i = tid; i < CIN * COUT; i += TB) Ws[i] = wmat[i];

    // --- load halo tile of x, pre-scaled by dinv(q) = a(gh)*a(gw), zero outside image ---
    const int h0 = by * TILE_H - 1;
    const int w0 = bx * TILE_W - 1;
    const float* xb = x + (size_t)b * CIN * HH * WW;
    for (int i = tid; i < XS_ELEMS; i += TB) {
        int col = i % HALO_W;
        int rc  = i / HALO_W;
        int row = rc % HALO_H;
        int c   = rc / HALO_H;
        int gh = h0 + row;
        int gw = w0 + col;
        float v = 0.0f;
        if ((unsigned)gh < HH && (unsigned)gw < WW) {
            v = xb[(size_t)c * (HH * WW) + gh * WW + gw] * (axis_a(gh) * axis_a(gw));
        }
        xs[i] = v;
    }
    __syncthreads();

    const int tx = tid & 31;
    const int ty = tid >> 5;
    const int gh = by * TILE_H + ty;
    const int gw = bx * TILE_W + tx;

    // 64 fp32 accumulators as 32 packed f32x2 (output pairs o, o+1)
    unsigned long long acc[COUT / 2];
    #pragma unroll
    for (int j = 0; j < COUT / 2; j++) acc[j] = 0ull;

    #pragma unroll 4
    for (int c = 0; c < CIN; c++) {
        const float* p = xs + c * (HALO_H * HALO_W) + ty * HALO_W + tx;
        // 9-point box sum of dinv-scaled x (the (A+I)D^{-1/2} part)
        float t = p[0] + p[1] + p[2]
                + p[HALO_W + 0] + p[HALO_W + 1] + p[HALO_W + 2]
                + p[2 * HALO_W + 0] + p[2 * HALO_W + 1] + p[2 * HALO_W + 2];

        unsigned long long t2;
        asm("mov.b64 %0, {%1, %1};" : "=l"(t2) : "f"(t));

        // W row for this c: 64 floats = 16 x 128-bit loads, each giving 2 packed f32x2 operands
        const ulonglong2* wrow = reinterpret_cast<const ulonglong2*>(Ws + c * COUT);
        #pragma unroll
        for (int j = 0; j < 16; j++) {
            ulonglong2 wp = wrow[j];
            asm("fma.rn.f32x2 %0, %1, %2, %0;" : "+l"(acc[2 * j + 0]) : "l"(t2), "l"(wp.x));
            asm("fma.rn.f32x2 %0, %1, %2, %0;" : "+l"(acc[2 * j + 1]) : "l"(t2), "l"(wp.y));
        }
    }

    // epilogue: scale by dinv(p), write out[b][o][gh][gw]
    const float dp = axis_a(gh) * axis_a(gw);
    float* outp = out + (size_t)b * COUT * HH * WW + (size_t)gh * WW + gw;
    #pragma unroll
    for (int j = 0; j < COUT / 2; j++) {
        float lo, hi;
        asm("mov.b64 {%0, %1}, %2;" : "=f"(lo), "=f"(hi) : "l"(acc[j]));
        outp[(size_t)(2 * j + 0) * (HH * WW)] = lo * dp;
        outp[(size_t)(2 * j + 1) * (HH * WW)] = hi * dp;
    }
}

extern "C" void kernel_launch(void* const* d_in, const int* in_sizes, int n_in,
                              void* d_out, int out_size)
{
    const float* x = (const float*)d_in[0];   // [4, 64, 512, 512]
    const float* w = (const float*)d_in[1];   // [1, 64, 64]
    float* out = (float*)d_out;               // [4, 64, 512, 512]

    cudaFuncSetAttribute(gcn_fused_kernel,
                         cudaFuncAttributeMaxDynamicSharedMemorySize, SMEM_BYTES);

    dim3 grid(WW / TILE_W, HH / TILE_H, 4);
    gcn_fused_kernel<<<grid, TB, SMEM_BYTES>>>(x, w, out);
}